// round 16
// baseline (speedup 1.0000x reference)
#include <cuda_runtime.h>
#include <cstdint>

#define MM    128   // padded image side
#define NP    64    // patch side
#define NC    4     // channels / positions
#define C0    32    // (M - N) / 2
#define RB    16    // rows per thread band
#define WROW0 11    // first staged image row (fixed layout)
#define WROWS 108   // stage capacity rows 11..118
#define WCOL0 8     // first staged image col (16B-aligned)
#define WCOLS 112   // stage capacity cols 8..119

__device__ __forceinline__ uint32_t smem_u32(const void* p) {
    uint32_t a;
    asm("{ .reg .u64 t; cvta.to.shared.u64 t, %1; cvt.u32.u64 %0, t; }"
        : "=r"(a) : "l"(p));
    return a;
}

// R14 structure (best known: 512 thr, 32 regs, 4 CTAs/SM = 64 warps, dynamic
// window -> smem -> LDS compute, write-back float2 stores) with ONE fix:
// no pre-fill barrier. All threads compute the window bounds redundantly
// from broadcast loads (dead temporaries), the fill starts immediately, and
// the post-fill wait+syncthreads covers spos visibility for compute.
__global__ __launch_bounds__(512, 4)
void extract_patches_kernel(const float* __restrict__ img,
                            const float* __restrict__ pos,
                            float* __restrict__ out)
{
    __shared__ __align__(16) float stage[WROWS * WCOLS];   // 48384 B
    __shared__ float spos[2 * NC];

    const int b = blockIdx.x;
    const float* I = img + (size_t)b * (MM * MM);
    const float* P = pos + (size_t)b * (2 * NC);

    const int lid  = threadIdx.x + 2 * threadIdx.y + 128 * threadIdx.z;
    const int wid  = lid >> 5;     // 16 warps
    const int lane = lid & 31;

    // Every thread derives the window bounds from uniform broadcast loads
    // (temporaries only; live range ends before the compute phase).
    int r_lo, r_hi, q_lo, q_hi;
    {
        int ymin = MM, ymax = 0, xmin = MM, xmax = 0;
#pragma unroll
        for (int c = 0; c < NC; c++) {
            float ox = __ldg(P + c);
            float oy = __ldg(P + NC + c);
            if (lid == c)      spos[c]      = ox;   // stage for compute phase
            if (lid == NC + c) spos[NC + c] = oy;
            // Pad one cell each side for per-element floor rounding slack.
            int yb = (int)floorf((float)C0 + oy);
            int xb = (int)floorf((float)C0 + ox);
            ymin = min(ymin, yb - 1);  ymax = max(ymax, yb + NP + 1);
            xmin = min(xmin, xb - 1);  xmax = max(xmax, xb + NP + 1);
        }
        // |shift|<20 -> bounds stay inside the fixed 108x112 stage.
        r_lo = ymin - WROW0;
        r_hi = ymax - WROW0;            // inclusive
        q_lo = (xmin - WCOL0) >> 2;     // first float4 chunk
        q_hi = (xmax - WCOL0) >> 2;     // last float4 chunk
    }

    // ---- Phase 1: stream the dynamic sub-window into smem (no pre-barrier)
    if (lane >= q_lo && lane <= q_hi) {
        for (int r = r_lo + wid; r <= r_hi; r += 16) {
            uint32_t sdst = smem_u32(stage) + (r * WCOLS + lane * 4) * 4;
            const float* gsrc = I + (WROW0 + r) * MM + WCOL0 + lane * 4;
            asm volatile("cp.async.cg.shared.global [%0], [%1], 16;"
                         :: "r"(sdst), "l"(gsrc) : "memory");
        }
    }
    asm volatile("cp.async.commit_group;" ::: "memory");
    asm volatile("cp.async.wait_group 0;" ::: "memory");
    __syncthreads();   // stage + spos now visible to all warps

    // block (2, 64, 4): tx = channel pair, ty = column, tz = 16-row band.
    const int col = threadIdx.y;
    const int i0  = threadIdx.z * RB;
    const int cb  = threadIdx.x * 2;

    // Per-channel setup. wy hoisted to a band constant (validated R7-R15).
    float wx[2], wy[2], hprev[2];
    int sb[2];
#pragma unroll
    for (int u = 0; u < 2; u++) {
        float xx = (float)(col + C0) + spos[cb + u];
        float x0 = floorf(xx);
        wx[u]    = xx - x0;
        int xi   = (int)x0;

        float yy = (float)(i0 + C0) + spos[NC + cb + u];
        float y0 = floorf(yy);
        wy[u]    = yy - y0;
        int yi   = (int)y0;

        sb[u] = (yi - WROW0) * WCOLS + (xi - WCOL0);
        float a0 = stage[sb[u]];
        float a1 = stage[sb[u] + 1];
        hprev[u] = fmaf(a1 - a0, wx[u], a0);   // H(top row)
    }

    // Output: (B, 64, 64, 4); warp-contiguous full-sector float2 stores.
    float* ob = out + ((size_t)b * (NP * NP) + (size_t)i0 * NP + col) * NC + cb;

#pragma unroll
    for (int k = 0; k < RB; k++) {
        float2 res;
#pragma unroll
        for (int u = 0; u < 2; u++) {
            int idx = sb[u] + (k + 1) * WCOLS;
            float b0 = stage[idx];
            float b1 = stage[idx + 1];
            float hnew = fmaf(b1 - b0, wx[u], b0);      // H(bottom row)
            float r    = fmaf(hnew - hprev[u], wy[u], hprev[u]);
            hprev[u]   = hnew;
            if (u == 0) res.x = r; else res.y = r;
        }
        // Write-back store (R10+ winner): L2 coalesces full lines.
        *reinterpret_cast<float2*>(ob + (size_t)k * (NP * NC)) = res;
    }
}

extern "C" void kernel_launch(void* const* d_in, const int* in_sizes, int n_in,
                              void* d_out, int out_size)
{
    const float* img = (const float*)d_in[0];   // padded_obj (B,128,128,1)
    const float* pos = (const float*)d_in[1];   // positions  (B,1,2,4)
    float* out = (float*)d_out;                 // (B,64,64,4)

    int B = in_sizes[0] / (MM * MM);
    dim3 block(2, 64, 4);
    extract_patches_kernel<<<B, block>>>(img, pos, out);
}

// round 17
// speedup vs baseline: 1.0188x; 1.0188x over previous
#include <cuda_runtime.h>
#include <cstdint>

#define MM    128   // padded image side
#define NP    64    // patch side
#define NC    4     // channels / positions
#define C0    32    // (M - N) / 2
#define WROW0 11    // first staged image row (fixed layout)
#define WROWS 108   // stage capacity rows 11..118
#define WCOL0 8     // first staged image col (16B-aligned)
#define WCOLS 112   // stage capacity cols 8..119

__device__ __forceinline__ uint32_t smem_u32(const void* p) {
    uint32_t a;
    asm("{ .reg .u64 t; cvta.to.shared.u64 t, %1; cvt.u32.u64 %0, t; }"
        : "=r"(a) : "l"(p));
    return a;
}

// R14 shell (512 thr, 32 regs, 4 CTAs/SM, dynamic window -> smem) with the
// compute remapped for minimum L1 wavefronts: block (64, 8), warp = 32
// CONSECUTIVE columns, each thread owns ALL 4 channels of one column for an
// 8-row band. Every LDS warp-instruction reads 32 consecutive floats (1
// wavefront, conflict-free) and each row ends in one contiguous STG.128 run
// (512B/warp): 12 wavefronts per 32col x 4ch x row vs R14's 16.
__global__ __launch_bounds__(512, 4)
void extract_patches_kernel(const float* __restrict__ img,
                            const float* __restrict__ pos,
                            float* __restrict__ out)
{
    __shared__ __align__(16) float stage[WROWS * WCOLS];   // 48384 B
    __shared__ float spos[2 * NC];
    __shared__ int   sbnd[4];        // r_lo, r_hi, q_lo, q_hi

    const int b = blockIdx.x;
    const float* I = img + (size_t)b * (MM * MM);

    const int lid  = threadIdx.x + 64 * threadIdx.y;
    const int wid  = lid >> 5;     // 16 warps
    const int lane = lid & 31;

    // One warp computes the dynamic window bounds + stages positions (R14).
    if (wid == 0) {
        if (lane < 2 * NC)
            spos[lane] = __ldg(pos + (size_t)b * (2 * NC) + lane);
        __syncwarp();
        if (lane == 0) {
            int ymin = MM, ymax = 0, xmin = MM, xmax = 0;
#pragma unroll
            for (int c = 0; c < NC; c++) {
                // Pad one cell each side for per-element floor rounding slack.
                int yb = (int)floorf((float)C0 + spos[NC + c]);
                int xb = (int)floorf((float)C0 + spos[c]);
                ymin = min(ymin, yb - 1);  ymax = max(ymax, yb + NP + 1);
                xmin = min(xmin, xb - 1);  xmax = max(xmax, xb + NP + 1);
            }
            // |shift|<20 -> bounds stay inside the fixed 108x112 stage.
            sbnd[0] = ymin - WROW0;
            sbnd[1] = ymax - WROW0;            // inclusive
            sbnd[2] = (xmin - WCOL0) >> 2;     // first float4 chunk
            sbnd[3] = (xmax - WCOL0) >> 2;     // last float4 chunk
        }
    }
    __syncthreads();

    // ---- Phase 1: stream the dynamic sub-window into smem ----
    {
        const int r_lo = sbnd[0], r_hi = sbnd[1];
        const int q_lo = sbnd[2], q_hi = sbnd[3];
        if (lane >= q_lo && lane <= q_hi) {
            for (int r = r_lo + wid; r <= r_hi; r += 16) {
                uint32_t sdst = smem_u32(stage) + (r * WCOLS + lane * 4) * 4;
                const float* gsrc = I + (WROW0 + r) * MM + WCOL0 + lane * 4;
                asm volatile("cp.async.cg.shared.global [%0], [%1], 16;"
                             :: "r"(sdst), "l"(gsrc) : "memory");
            }
        }
        asm volatile("cp.async.commit_group;" ::: "memory");
        asm volatile("cp.async.wait_group 0;" ::: "memory");
    }
    __syncthreads();

    // block (64, 8): tx = column (warp = 32 consecutive cols), ty = 8-row band.
    const int col = threadIdx.x;
    const int i0  = threadIdx.y * 8;

    // Per-channel setup, all 4 channels in this thread. wy hoisted to a
    // band constant (validated R7-R16; bilinear continuity bounds the ulp
    // effects at ~1e-6 << 1e-3).
    float wx[NC], wy[NC], hprev[NC];
    int sb[NC];
#pragma unroll
    for (int c = 0; c < NC; c++) {
        float xx = (float)(col + C0) + spos[c];
        float x0 = floorf(xx);
        wx[c]    = xx - x0;
        int xi   = (int)x0;

        float yy = (float)(i0 + C0) + spos[NC + c];
        float y0 = floorf(yy);
        wy[c]    = yy - y0;
        int yi   = (int)y0;

        sb[c] = (yi - WROW0) * WCOLS + (xi - WCOL0);
        float a0 = stage[sb[c]];
        float a1 = stage[sb[c] + 1];
        hprev[c] = fmaf(a1 - a0, wx[c], a0);   // H(top row)
    }

    // Output: (B, 64, 64, 4) = float4 per (row, col); warp stores one
    // contiguous 512B STG.128 run per row.
    float4* ob = reinterpret_cast<float4*>(out) +
                 (size_t)b * (NP * NP) + (size_t)i0 * NP + col;

#pragma unroll
    for (int k = 0; k < 8; k++) {
        float4 res;
        float* rp = reinterpret_cast<float*>(&res);
#pragma unroll
        for (int c = 0; c < NC; c++) {
            int idx = sb[c] + (k + 1) * WCOLS;   // compile-time immediates
            float b0 = stage[idx];
            float b1 = stage[idx + 1];
            float hnew = fmaf(b1 - b0, wx[c], b0);      // H(bottom row)
            rp[c]     = fmaf(hnew - hprev[c], wy[c], hprev[c]);
            hprev[c]  = hnew;
        }
        // Write-back store (R10+ winner): L2 coalesces full lines.
        ob[(size_t)k * NP] = res;
    }
}

extern "C" void kernel_launch(void* const* d_in, const int* in_sizes, int n_in,
                              void* d_out, int out_size)
{
    const float* img = (const float*)d_in[0];   // padded_obj (B,128,128,1)
    const float* pos = (const float*)d_in[1];   // positions  (B,1,2,4)
    float* out = (float*)d_out;                 // (B,64,64,4)

    int B = in_sizes[0] / (MM * MM);
    dim3 block(64, 8);
    extract_patches_kernel<<<B, block>>>(img, pos, out);
}